// round 15
// baseline (speedup 1.0000x reference)
#include <cuda_runtime.h>
#include <cuda_fp16.h>
#include <cstdint>

// ============================================================================
// out[i] = x[i] + sum_j adj[i,j] * x[j]  ==  (adj + I) @ x,  N=16384, D=128
//
// compute_103 PTX target => NO tcgen05 / NO cp.async.bulk.tensor ('a' features).
// Baseline plan: fp16-reinterpret trick + mma.sync HMMA + 1-D cp.async.bulk
// (plain bulk copy, sm_90 baseline, still uses the TMA engine for bandwidth).
//
// int32 v in {0,1} = bytes [v,0,0,0] = fp16 pair (v*2^-24, +0.0).  adj IS a
// [16384 x 32768] fp16 matrix with exact zeros at odd k.  B = x expanded to
// fp16 (zeros at odd k), fp32 accumulate, epilogue scales by 2^24 (exact).
// ============================================================================

static constexpr int NROWS   = 16384;
static constexpr int DCOLS   = 128;
static constexpr int KITERS  = 256;     // 32768 f16 K / 128 per tile
static constexpr int STAGES  = 3;

static constexpr int A_ROW_GM   = 65536;          // adj row bytes
static constexpr int A_ROW_SM   = 272;            // 256 data + 16 pad (bank shift)
static constexpr int A_BYTES    = 128 * A_ROW_SM; // 34816
static constexpr int B_BYTES    = 32768;          // 128 n x 128 k fp16 (swizzled)
static constexpr int STAGE_BYTES = A_BYTES + B_BYTES;      // 67584
static constexpr int BAR_OFF    = STAGES * STAGE_BYTES;    // 202752
static constexpr int SMEM_TOTAL = BAR_OFF + 64;            // 202816 < 227KB

// 8 MB scratch, blocked layout: block t (k-tile) = 32KB contiguous:
//   [n=0..127][k=0..127] fp16, word (n, kkpair p): {f16(x[t*64+p][n]), 0}
//   16B chunks XOR-swizzled: chunk' = chunk ^ (n & 7)
__device__ __align__(128) uint4 g_B[KITERS * 2048];   // 8 MB

// ---------------------------------------------------------------------------
__device__ __forceinline__ uint32_t smem_u32(const void* p) {
    return (uint32_t)__cvta_generic_to_shared(p);
}
__device__ __forceinline__ void mbar_init(uint32_t a, uint32_t cnt) {
    asm volatile("mbarrier.init.shared.b64 [%0], %1;" :: "r"(a), "r"(cnt) : "memory");
}
__device__ __forceinline__ void mbar_expect_tx(uint32_t a, uint32_t bytes) {
    asm volatile("mbarrier.arrive.expect_tx.shared.b64 _, [%0], %1;"
                 :: "r"(a), "r"(bytes) : "memory");
}
__device__ __forceinline__ void mbar_arrive(uint32_t a) {
    asm volatile("mbarrier.arrive.shared.b64 _, [%0];" :: "r"(a) : "memory");
}
__device__ __forceinline__ void mbar_wait(uint32_t a, uint32_t parity) {
    uint32_t done = 0;
    while (!done) {
        asm volatile(
            "{\n\t.reg .pred p;\n\t"
            "mbarrier.try_wait.parity.acquire.cta.shared::cta.b64 p, [%1], %2, 0x989680;\n\t"
            "selp.b32 %0, 1, 0, p;\n\t}"
            : "=r"(done) : "r"(a), "r"(parity) : "memory");
    }
}
// Plain 1-D bulk copy gmem->smem (baseline sm_90, runs on the TMA engine)
__device__ __forceinline__ void bulk_g2s(uint32_t dst, const void* src,
                                         uint32_t bytes, uint32_t mbar) {
    asm volatile(
        "cp.async.bulk.shared::cluster.global.mbarrier::complete_tx::bytes "
        "[%0], [%1], %2, [%3];"
        :: "r"(dst), "l"(src), "r"(bytes), "r"(mbar) : "memory");
}
__device__ __forceinline__ void ldsm_x4(uint32_t& r0, uint32_t& r1,
                                        uint32_t& r2, uint32_t& r3, uint32_t addr) {
    asm volatile("ldmatrix.sync.aligned.m8n8.x4.shared.b16 {%0,%1,%2,%3}, [%4];"
                 : "=r"(r0), "=r"(r1), "=r"(r2), "=r"(r3) : "r"(addr));
}
__device__ __forceinline__ void mma16816(float* c,
                                         uint32_t a0, uint32_t a1, uint32_t a2, uint32_t a3,
                                         uint32_t b0, uint32_t b1) {
    asm volatile(
        "mma.sync.aligned.m16n8k16.row.col.f32.f16.f16.f32 "
        "{%0,%1,%2,%3}, {%4,%5,%6,%7}, {%8,%9}, {%0,%1,%2,%3};"
        : "+f"(c[0]), "+f"(c[1]), "+f"(c[2]), "+f"(c[3])
        : "r"(a0), "r"(a1), "r"(a2), "r"(a3), "r"(b0), "r"(b1));
}

// ---------------------------------------------------------------------------
// Prep: x (fp32 [N, D]) -> g_B blocked/swizzled fp16 with interleaved zeros.
// idx: n fast (coalesced x reads), each thread writes one 16B chunk.
// ---------------------------------------------------------------------------
__global__ void prep_b_kernel(const float* __restrict__ x) {
    int idx = blockIdx.x * blockDim.x + threadIdx.x;   // 0 .. 524287
    int n  = idx & 127;
    int kg = (idx >> 7) & 15;      // 16B chunk index (4 kk-pairs)
    int t  = idx >> 11;            // k-tile 0..255
    int j0 = t * 64 + kg * 4;
    uint32_t w0 = (uint32_t)__half_as_ushort(__float2half_rn(x[(j0 + 0) * DCOLS + n]));
    uint32_t w1 = (uint32_t)__half_as_ushort(__float2half_rn(x[(j0 + 1) * DCOLS + n]));
    uint32_t w2 = (uint32_t)__half_as_ushort(__float2half_rn(x[(j0 + 2) * DCOLS + n]));
    uint32_t w3 = (uint32_t)__half_as_ushort(__float2half_rn(x[(j0 + 3) * DCOLS + n]));
    int chunk = kg ^ (n & 7);
    uint4* dst = reinterpret_cast<uint4*>(
        reinterpret_cast<char*>(g_B) + (size_t)t * B_BYTES + n * 256 + chunk * 16);
    *dst = make_uint4(w0, w1, w2, w3);
}

// ---------------------------------------------------------------------------
// GEMM: 128 CTAs x 256 threads. Per CTA: M=128, N=128, K=32768 f16.
// 3-stage bulk-copy pipeline; warps 4x2 (M x N), warp tile 32x64, HMMA 16816.
// ---------------------------------------------------------------------------
__global__ void __launch_bounds__(256, 1) gnn_gemm_kernel(
    const char* __restrict__ adj,
    const float* __restrict__ x,
    float* __restrict__ out)
{
    extern __shared__ __align__(128) char smem_buf[];
    const uint32_t sb     = smem_u32(smem_buf);
    const uint32_t FULL0  = sb + BAR_OFF;         // 3 x 8B
    const uint32_t EMPTY0 = sb + BAR_OFF + 24;    // 3 x 8B

    const int tid  = threadIdx.x;
    const int lane = tid & 31;
    const int w    = tid >> 5;
    const int wm   = (w & 3) * 32;    // warp M offset
    const int wn   = (w >> 2) * 64;   // warp N offset
    const int llo  = lane & 15;
    const int lhi  = lane >> 4;
    const int mrow = blockIdx.x * 128;

    if (tid == 0) {
        for (int s = 0; s < STAGES; s++) {
            mbar_init(FULL0 + 8 * s, 1);       // expect_tx arrive only
            mbar_init(EMPTY0 + 8 * s, 256);    // all threads arrive
        }
        asm volatile("fence.mbarrier_init.release.cluster;" ::: "memory");
    }
    __syncthreads();

    // ---- prologue: fill stages 0..2 with tiles 0..2 (buffers start empty) ----
    for (int s = 0; s < STAGES; s++) {
        if (tid == 0) mbar_expect_tx(FULL0 + 8 * s, A_BYTES / A_ROW_SM * 256 + B_BYTES);
        if (tid < 128)
            bulk_g2s(sb + s * STAGE_BYTES + tid * A_ROW_SM,
                     adj + (size_t)(mrow + tid) * A_ROW_GM + (size_t)s * 256,
                     256, FULL0 + 8 * s);
        if (tid == 0)
            bulk_g2s(sb + s * STAGE_BYTES + A_BYTES,
                     reinterpret_cast<const char*>(g_B) + (size_t)s * B_BYTES,
                     B_BYTES, FULL0 + 8 * s);
    }

    float acc[2][8][4];
    #pragma unroll
    for (int a = 0; a < 2; a++)
        #pragma unroll
        for (int j = 0; j < 8; j++)
            #pragma unroll
            for (int q = 0; q < 4; q++) acc[a][j][q] = 0.0f;

    // per-thread A ldmatrix base offsets (row pad 272B -> conflict-free)
    const uint32_t aoff0 = (uint32_t)(wm + llo) * A_ROW_SM + (uint32_t)lhi * 16;
    const uint32_t aoff1 = aoff0 + 16 * A_ROW_SM;

    int cs = 0, cph = 0;        // consumer cursor
    int ps = 0, pph = 0;        // producer cursor (first reuse waits phase-0 flip)
    int nt = STAGES;            // next tile to fetch

    for (int it = 0; it < KITERS; ++it) {
        mbar_wait(FULL0 + 8 * cs, (uint32_t)cph);

        const uint32_t Ab = sb + cs * STAGE_BYTES;
        const uint32_t Bb = Ab + A_BYTES;

        #pragma unroll
        for (int k16 = 0; k16 < 8; ++k16) {
            uint32_t A0[4], A1[4];
            ldsm_x4(A0[0], A0[1], A0[2], A0[3], Ab + aoff0 + k16 * 32);
            ldsm_x4(A1[0], A1[1], A1[2], A1[3], Ab + aoff1 + k16 * 32);

            uint32_t bf[8][2];
            #pragma unroll
            for (int bq = 0; bq < 4; ++bq) {
                int n = wn + bq * 16 + llo;
                uint32_t chunk = (uint32_t)((k16 * 2 + lhi) ^ (n & 7));
                uint32_t r0, r1, r2, r3;
                ldsm_x4(r0, r1, r2, r3, Bb + (uint32_t)n * 256 + chunk * 16);
                bf[2 * bq + 0][0] = r0; bf[2 * bq + 0][1] = r2;   // n0-7  of group
                bf[2 * bq + 1][0] = r1; bf[2 * bq + 1][1] = r3;   // n8-15 of group
            }
            #pragma unroll
            for (int j = 0; j < 8; ++j) {
                mma16816(acc[0][j], A0[0], A0[1], A0[2], A0[3], bf[j][0], bf[j][1]);
                mma16816(acc[1][j], A1[0], A1[1], A1[2], A1[3], bf[j][0], bf[j][1]);
            }
        }
        mbar_arrive(EMPTY0 + 8 * cs);

        // ---- prefetch tile nt into stage ps ----
        if (nt < KITERS) {
            if (tid < 128) {
                mbar_wait(EMPTY0 + 8 * ps, (uint32_t)pph);
                if (tid == 0) mbar_expect_tx(FULL0 + 8 * ps, 128 * 256 + B_BYTES);
                bulk_g2s(sb + ps * STAGE_BYTES + tid * A_ROW_SM,
                         adj + (size_t)(mrow + tid) * A_ROW_GM + (size_t)nt * 256,
                         256, FULL0 + 8 * ps);
                if (tid == 0)
                    bulk_g2s(sb + ps * STAGE_BYTES + A_BYTES,
                             reinterpret_cast<const char*>(g_B) + (size_t)nt * B_BYTES,
                             B_BYTES, FULL0 + 8 * ps);
            }
            if (++ps == STAGES) { ps = 0; pph ^= 1; }
        }
        ++nt;
        if (++cs == STAGES) { cs = 0; cph ^= 1; }
    }

    // ---- epilogue: out = x + 2^24 * acc ----
    const float S = 16777216.0f;
    const int g = lane >> 2, q = lane & 3;
    #pragma unroll
    for (int am = 0; am < 2; ++am) {
        const int r0 = mrow + wm + am * 16 + g;
        const float* x0 = x + (size_t)r0 * DCOLS;
        const float* x1 = x0 + 8 * DCOLS;
        float* o0 = out + (size_t)r0 * DCOLS;
        float* o1 = o0 + 8 * DCOLS;
        #pragma unroll
        for (int j = 0; j < 8; ++j) {
            const int c = wn + j * 8 + q * 2;
            float2 v0, v1;
            v0.x = fmaf(S, acc[am][j][0], x0[c]);
            v0.y = fmaf(S, acc[am][j][1], x0[c + 1]);
            v1.x = fmaf(S, acc[am][j][2], x1[c]);
            v1.y = fmaf(S, acc[am][j][3], x1[c + 1]);
            *reinterpret_cast<float2*>(o0 + c) = v0;
            *reinterpret_cast<float2*>(o1 + c) = v1;
        }
    }
}

// ---------------------------------------------------------------------------
extern "C" void kernel_launch(void* const* d_in, const int* in_sizes, int n_in,
                              void* d_out, int out_size) {
    const float* x;
    const void*  adj;
    if (in_sizes[0] == NROWS * DCOLS) { x = (const float*)d_in[0]; adj = d_in[1]; }
    else                              { x = (const float*)d_in[1]; adj = d_in[0]; }

    prep_b_kernel<<<2048, 256>>>(x);

    cudaFuncSetAttribute(gnn_gemm_kernel,
                         cudaFuncAttributeMaxDynamicSharedMemorySize, SMEM_TOTAL);
    gnn_gemm_kernel<<<128, 256, SMEM_TOTAL>>>(
        (const char*)adj, x, (float*)d_out);
}

// round 16
// speedup vs baseline: 1.0008x; 1.0008x over previous
#include <cuda_runtime.h>
#include <cuda_fp16.h>
#include <cstdint>

// ============================================================================
// out[i] = x[i] + sum_j adj[i,j] * x[j]  ==  (adj + I) @ x,  N=16384, D=128
//
// compute_103 PTX target => NO tcgen05 / NO cp.async.bulk.tensor ('a' features).
// Baseline plan: fp16-reinterpret trick + mma.sync HMMA + 1-D cp.async.bulk
// (plain bulk copy, sm_90 baseline, still uses the TMA engine for bandwidth).
//
// int32 v in {0,1} = bytes [v,0,0,0] = fp16 pair (v*2^-24, +0.0).  adj IS a
// [16384 x 32768] fp16 matrix with exact zeros at odd k.  B = x expanded to
// fp16 (zeros at odd k), fp32 accumulate, epilogue scales by 2^24 (exact).
// ============================================================================

static constexpr int NROWS   = 16384;
static constexpr int DCOLS   = 128;
static constexpr int KITERS  = 256;     // 32768 f16 K / 128 per tile
static constexpr int STAGES  = 3;

static constexpr int A_ROW_GM   = 65536;          // adj row bytes
static constexpr int A_ROW_SM   = 272;            // 256 data + 16 pad (bank shift)
static constexpr int A_BYTES    = 128 * A_ROW_SM; // 34816
static constexpr int B_BYTES    = 32768;          // 128 n x 128 k fp16 (swizzled)
static constexpr int STAGE_BYTES = A_BYTES + B_BYTES;      // 67584
static constexpr int BAR_OFF    = STAGES * STAGE_BYTES;    // 202752
static constexpr int SMEM_TOTAL = BAR_OFF + 64;            // 202816 < 227KB

// 8 MB scratch, blocked layout: block t (k-tile) = 32KB contiguous:
//   [n=0..127][k=0..127] fp16, word (n, kkpair p): {f16(x[t*64+p][n]), 0}
//   16B chunks XOR-swizzled: chunk' = chunk ^ (n & 7)
__device__ __align__(128) uint4 g_B[KITERS * 2048];   // 8 MB

// ---------------------------------------------------------------------------
__device__ __forceinline__ uint32_t smem_u32(const void* p) {
    return (uint32_t)__cvta_generic_to_shared(p);
}
__device__ __forceinline__ void mbar_init(uint32_t a, uint32_t cnt) {
    asm volatile("mbarrier.init.shared.b64 [%0], %1;" :: "r"(a), "r"(cnt) : "memory");
}
__device__ __forceinline__ void mbar_expect_tx(uint32_t a, uint32_t bytes) {
    asm volatile("mbarrier.arrive.expect_tx.shared.b64 _, [%0], %1;"
                 :: "r"(a), "r"(bytes) : "memory");
}
__device__ __forceinline__ void mbar_arrive(uint32_t a) {
    asm volatile("mbarrier.arrive.shared.b64 _, [%0];" :: "r"(a) : "memory");
}
__device__ __forceinline__ void mbar_wait(uint32_t a, uint32_t parity) {
    uint32_t done = 0;
    while (!done) {
        asm volatile(
            "{\n\t.reg .pred p;\n\t"
            "mbarrier.try_wait.parity.acquire.cta.shared::cta.b64 p, [%1], %2, 0x989680;\n\t"
            "selp.b32 %0, 1, 0, p;\n\t}"
            : "=r"(done) : "r"(a), "r"(parity) : "memory");
    }
}
// Plain 1-D bulk copy gmem->smem (baseline sm_90, runs on the TMA engine)
__device__ __forceinline__ void bulk_g2s(uint32_t dst, const void* src,
                                         uint32_t bytes, uint32_t mbar) {
    asm volatile(
        "cp.async.bulk.shared::cluster.global.mbarrier::complete_tx::bytes "
        "[%0], [%1], %2, [%3];"
        :: "r"(dst), "l"(src), "r"(bytes), "r"(mbar) : "memory");
}
__device__ __forceinline__ void ldsm_x4(uint32_t& r0, uint32_t& r1,
                                        uint32_t& r2, uint32_t& r3, uint32_t addr) {
    asm volatile("ldmatrix.sync.aligned.m8n8.x4.shared.b16 {%0,%1,%2,%3}, [%4];"
                 : "=r"(r0), "=r"(r1), "=r"(r2), "=r"(r3) : "r"(addr));
}
__device__ __forceinline__ void mma16816(float* c,
                                         uint32_t a0, uint32_t a1, uint32_t a2, uint32_t a3,
                                         uint32_t b0, uint32_t b1) {
    asm volatile(
        "mma.sync.aligned.m16n8k16.row.col.f32.f16.f16.f32 "
        "{%0,%1,%2,%3}, {%4,%5,%6,%7}, {%8,%9}, {%0,%1,%2,%3};"
        : "+f"(c[0]), "+f"(c[1]), "+f"(c[2]), "+f"(c[3])
        : "r"(a0), "r"(a1), "r"(a2), "r"(a3), "r"(b0), "r"(b1));
}

// ---------------------------------------------------------------------------
// Prep: x (fp32 [N, D]) -> g_B blocked/swizzled fp16 with interleaved zeros.
// idx: n fast (coalesced x reads), each thread writes one 16B chunk.
// ---------------------------------------------------------------------------
__global__ void prep_b_kernel(const float* __restrict__ x) {
    int idx = blockIdx.x * blockDim.x + threadIdx.x;   // 0 .. 524287
    int n  = idx & 127;
    int kg = (idx >> 7) & 15;      // 16B chunk index (4 kk-pairs)
    int t  = idx >> 11;            // k-tile 0..255
    int j0 = t * 64 + kg * 4;
    uint32_t w0 = (uint32_t)__half_as_ushort(__float2half_rn(x[(j0 + 0) * DCOLS + n]));
    uint32_t w1 = (uint32_t)__half_as_ushort(__float2half_rn(x[(j0 + 1) * DCOLS + n]));
    uint32_t w2 = (uint32_t)__half_as_ushort(__float2half_rn(x[(j0 + 2) * DCOLS + n]));
    uint32_t w3 = (uint32_t)__half_as_ushort(__float2half_rn(x[(j0 + 3) * DCOLS + n]));
    int chunk = kg ^ (n & 7);
    uint4* dst = reinterpret_cast<uint4*>(
        reinterpret_cast<char*>(g_B) + (size_t)t * B_BYTES + n * 256 + chunk * 16);
    *dst = make_uint4(w0, w1, w2, w3);
}

// ---------------------------------------------------------------------------
// GEMM: 128 CTAs x 256 threads. Per CTA: M=128, N=128, K=32768 f16.
// 3-stage bulk-copy pipeline; warps 4x2 (M x N), warp tile 32x64, HMMA 16816.
// ---------------------------------------------------------------------------
__global__ void __launch_bounds__(256, 1) gnn_gemm_kernel(
    const char* __restrict__ adj,
    const float* __restrict__ x,
    float* __restrict__ out)
{
    extern __shared__ __align__(128) char smem_buf[];
    const uint32_t sb     = smem_u32(smem_buf);
    const uint32_t FULL0  = sb + BAR_OFF;         // 3 x 8B
    const uint32_t EMPTY0 = sb + BAR_OFF + 24;    // 3 x 8B

    const int tid  = threadIdx.x;
    const int lane = tid & 31;
    const int w    = tid >> 5;
    const int wm   = (w & 3) * 32;    // warp M offset
    const int wn   = (w >> 2) * 64;   // warp N offset
    const int llo  = lane & 15;
    const int lhi  = lane >> 4;
    const int mrow = blockIdx.x * 128;

    if (tid == 0) {
        for (int s = 0; s < STAGES; s++) {
            mbar_init(FULL0 + 8 * s, 1);       // expect_tx arrive only
            mbar_init(EMPTY0 + 8 * s, 256);    // all threads arrive
        }
        asm volatile("fence.mbarrier_init.release.cluster;" ::: "memory");
    }
    __syncthreads();

    // ---- prologue: fill stages 0..2 with tiles 0..2 (buffers start empty) ----
    for (int s = 0; s < STAGES; s++) {
        if (tid == 0) mbar_expect_tx(FULL0 + 8 * s, A_BYTES / A_ROW_SM * 256 + B_BYTES);
        if (tid < 128)
            bulk_g2s(sb + s * STAGE_BYTES + tid * A_ROW_SM,
                     adj + (size_t)(mrow + tid) * A_ROW_GM + (size_t)s * 256,
                     256, FULL0 + 8 * s);
        if (tid == 0)
            bulk_g2s(sb + s * STAGE_BYTES + A_BYTES,
                     reinterpret_cast<const char*>(g_B) + (size_t)s * B_BYTES,
                     B_BYTES, FULL0 + 8 * s);
    }

    float acc[2][8][4];
    #pragma unroll
    for (int a = 0; a < 2; a++)
        #pragma unroll
        for (int j = 0; j < 8; j++)
            #pragma unroll
            for (int q = 0; q < 4; q++) acc[a][j][q] = 0.0f;

    // per-thread A ldmatrix base offsets (row pad 272B -> conflict-free)
    const uint32_t aoff0 = (uint32_t)(wm + llo) * A_ROW_SM + (uint32_t)lhi * 16;
    const uint32_t aoff1 = aoff0 + 16 * A_ROW_SM;

    int cs = 0, cph = 0;        // consumer cursor
    int ps = 0, pph = 0;        // producer cursor (first reuse waits phase-0 flip)
    int nt = STAGES;            // next tile to fetch

    for (int it = 0; it < KITERS; ++it) {
        mbar_wait(FULL0 + 8 * cs, (uint32_t)cph);

        const uint32_t Ab = sb + cs * STAGE_BYTES;
        const uint32_t Bb = Ab + A_BYTES;

        #pragma unroll
        for (int k16 = 0; k16 < 8; ++k16) {
            uint32_t A0[4], A1[4];
            ldsm_x4(A0[0], A0[1], A0[2], A0[3], Ab + aoff0 + k16 * 32);
            ldsm_x4(A1[0], A1[1], A1[2], A1[3], Ab + aoff1 + k16 * 32);

            uint32_t bf[8][2];
            #pragma unroll
            for (int bq = 0; bq < 4; ++bq) {
                int n = wn + bq * 16 + llo;
                uint32_t chunk = (uint32_t)((k16 * 2 + lhi) ^ (n & 7));
                uint32_t r0, r1, r2, r3;
                ldsm_x4(r0, r1, r2, r3, Bb + (uint32_t)n * 256 + chunk * 16);
                bf[2 * bq + 0][0] = r0; bf[2 * bq + 0][1] = r2;   // n0-7  of group
                bf[2 * bq + 1][0] = r1; bf[2 * bq + 1][1] = r3;   // n8-15 of group
            }
            #pragma unroll
            for (int j = 0; j < 8; ++j) {
                mma16816(acc[0][j], A0[0], A0[1], A0[2], A0[3], bf[j][0], bf[j][1]);
                mma16816(acc[1][j], A1[0], A1[1], A1[2], A1[3], bf[j][0], bf[j][1]);
            }
        }
        mbar_arrive(EMPTY0 + 8 * cs);

        // ---- prefetch tile nt into stage ps ----
        if (nt < KITERS) {
            if (tid < 128) {
                mbar_wait(EMPTY0 + 8 * ps, (uint32_t)pph);
                if (tid == 0) mbar_expect_tx(FULL0 + 8 * ps, 128 * 256 + B_BYTES);
                bulk_g2s(sb + ps * STAGE_BYTES + tid * A_ROW_SM,
                         adj + (size_t)(mrow + tid) * A_ROW_GM + (size_t)nt * 256,
                         256, FULL0 + 8 * ps);
                if (tid == 0)
                    bulk_g2s(sb + ps * STAGE_BYTES + A_BYTES,
                             reinterpret_cast<const char*>(g_B) + (size_t)nt * B_BYTES,
                             B_BYTES, FULL0 + 8 * ps);
            }
            if (++ps == STAGES) { ps = 0; pph ^= 1; }
        }
        ++nt;
        if (++cs == STAGES) { cs = 0; cph ^= 1; }
    }

    // ---- epilogue: out = x + 2^24 * acc ----
    const float S = 16777216.0f;
    const int g = lane >> 2, q = lane & 3;
    #pragma unroll
    for (int am = 0; am < 2; ++am) {
        const int r0 = mrow + wm + am * 16 + g;
        const float* x0 = x + (size_t)r0 * DCOLS;
        const float* x1 = x0 + 8 * DCOLS;
        float* o0 = out + (size_t)r0 * DCOLS;
        float* o1 = o0 + 8 * DCOLS;
        #pragma unroll
        for (int j = 0; j < 8; ++j) {
            const int c = wn + j * 8 + q * 2;
            float2 v0, v1;
            v0.x = fmaf(S, acc[am][j][0], x0[c]);
            v0.y = fmaf(S, acc[am][j][1], x0[c + 1]);
            v1.x = fmaf(S, acc[am][j][2], x1[c]);
            v1.y = fmaf(S, acc[am][j][3], x1[c + 1]);
            *reinterpret_cast<float2*>(o0 + c) = v0;
            *reinterpret_cast<float2*>(o1 + c) = v1;
        }
    }
}

// ---------------------------------------------------------------------------
extern "C" void kernel_launch(void* const* d_in, const int* in_sizes, int n_in,
                              void* d_out, int out_size) {
    const float* x;
    const void*  adj;
    if (in_sizes[0] == NROWS * DCOLS) { x = (const float*)d_in[0]; adj = d_in[1]; }
    else                              { x = (const float*)d_in[1]; adj = d_in[0]; }

    prep_b_kernel<<<2048, 256>>>(x);

    cudaFuncSetAttribute(gnn_gemm_kernel,
                         cudaFuncAttributeMaxDynamicSharedMemorySize, SMEM_TOTAL);
    gnn_gemm_kernel<<<128, 256, SMEM_TOTAL>>>(
        (const char*)adj, x, (float*)d_out);
}